// round 4
// baseline (speedup 1.0000x reference)
#include <cuda_runtime.h>
#include <cstdint>
#include <cstddef>
#include <cmath>

// Problem constants
#define T_STEPS 1000
#define BATCH   64
#define NDIM    512
#define KDIM    512
#define MROWS   (BATCH * T_STEPS)   // 64000

static constexpr size_t PLANE      = (size_t)BATCH * NDIM;          // 32768
static constexpr size_t STATES_OFF = (size_t)T_STEPS * PLANE;       // outputs plane elems
static constexpr size_t DEC_OFF    = STATES_OFF + 3 * STATES_OFF;   // after states [T,3,B,N]

// Scratch
__device__ __align__(16) float g_I[(size_t)MROWS * NDIM];
__device__ float g_r[T_STEPS * BATCH];

// ---------------------------------------------------------------------------
// tf32 helpers (sm_80+ compatible)
// ---------------------------------------------------------------------------
__device__ __forceinline__ uint32_t tf32_rna_bits(float x) {
    uint32_t u;
    asm("cvt.rna.tf32.f32 %0, %1;" : "=r"(u) : "f"(x));
    return u;
}

__device__ __forceinline__ void split_bits(float v, uint32_t& h, uint32_t& l) {
    h = tf32_rna_bits(v);
    l = tf32_rna_bits(v - __uint_as_float(h));
}

__device__ __forceinline__ void mma_tf32(float* c, const uint32_t* a, const uint32_t* b) {
    asm volatile(
        "mma.sync.aligned.m16n8k8.row.col.f32.tf32.tf32.f32 "
        "{%0,%1,%2,%3}, {%4,%5,%6,%7}, {%8,%9}, {%0,%1,%2,%3};\n"
        : "+f"(c[0]), "+f"(c[1]), "+f"(c[2]), "+f"(c[3])
        : "r"(a[0]), "r"(a[1]), "r"(a[2]), "r"(a[3]), "r"(b[0]), "r"(b[1]));
}

__device__ __forceinline__ void cp_async16(uint32_t smem_dst, const void* gptr) {
    asm volatile("cp.async.cg.shared.global [%0], [%1], 16;"
                 :: "r"(smem_dst), "l"(gptr) : "memory");
}
#define CP_COMMIT() asm volatile("cp.async.commit_group;" ::: "memory")
#define CP_WAIT(N)  asm volatile("cp.async.wait_group %0;" :: "n"(N) : "memory")

// ---------------------------------------------------------------------------
// Kernel 1: I = X @ W1^T  (NT GEMM) via mma.sync tf32, 3-product split.
// CTA 128x128, BK=32, 8 warps (4x2), warp tile 32x64.
// smem: raw f32 tiles only (split done in registers): per stage
//   A[128][36] + B[128][36] = 9216 floats = 36KB; 4 stages = 144KB.
// cp.async 4-stage pipeline, 3 chunks in flight.
// ---------------------------------------------------------------------------
#define STRF   36
#define ATILEF (128 * STRF)        // floats per A (or B) sub-tile
#define STAGEF (2 * ATILEF)        // floats per stage
#define NCHUNK 16

__device__ __forceinline__ void issue_chunk(uint32_t smem_u32_base, int stage,
                                            const float* __restrict__ xptr,
                                            const float* __restrict__ wptr,
                                            int ck, int row, int kb)
{
    const uint32_t sA = smem_u32_base + (uint32_t)(stage * STAGEF + row * STRF + kb) * 4u;
    const uint32_t sB = sA + (uint32_t)ATILEF * 4u;
    const float* xs = xptr + ck * 32;
    const float* ws = wptr + ck * 32;
    #pragma unroll
    for (int j = 0; j < 4; j++) cp_async16(sA + j * 16, xs + j * 4);
    #pragma unroll
    for (int j = 0; j < 4; j++) cp_async16(sB + j * 16, ws + j * 4);
}

__device__ __forceinline__ void compute_chunk(const float* __restrict__ buf,
                                              float (&acc)[2][8][4],
                                              int wm, int wn, int lane)
{
    const float* sA = buf;
    const float* sB = buf + ATILEF;
    const int lq = lane >> 2;        // 0..7
    const int lr = lane & 3;         // 0..3

    #pragma unroll
    for (int kk = 0; kk < 32; kk += 8) {
        const int c0 = kk + lr;
        uint32_t Ah[2][4], Al[2][4], Bh[8][2], Bl[8][2];
        #pragma unroll
        for (int mt = 0; mt < 2; mt++) {
            const int r0 = wm * 32 + mt * 16 + lq;
            split_bits(sA[r0 * STRF + c0],           Ah[mt][0], Al[mt][0]);
            split_bits(sA[(r0 + 8) * STRF + c0],     Ah[mt][1], Al[mt][1]);
            split_bits(sA[r0 * STRF + c0 + 4],       Ah[mt][2], Al[mt][2]);
            split_bits(sA[(r0 + 8) * STRF + c0 + 4], Ah[mt][3], Al[mt][3]);
        }
        #pragma unroll
        for (int nt = 0; nt < 8; nt++) {
            const int nr = wn * 64 + nt * 8 + lq;
            split_bits(sB[nr * STRF + c0],     Bh[nt][0], Bl[nt][0]);
            split_bits(sB[nr * STRF + c0 + 4], Bh[nt][1], Bl[nt][1]);
        }
        #pragma unroll
        for (int mt = 0; mt < 2; mt++)
            #pragma unroll
            for (int nt = 0; nt < 8; nt++) {
                mma_tf32(acc[mt][nt], Ah[mt], Bh[nt]);
                mma_tf32(acc[mt][nt], Ah[mt], Bl[nt]);
                mma_tf32(acc[mt][nt], Al[mt], Bh[nt]);
            }
    }
}

__global__ __launch_bounds__(256, 1) void gemm_tf32_kernel(const float* __restrict__ X,
                                                           const float* __restrict__ W)
{
    extern __shared__ float smem[];          // 4 stages * 9216 floats
    const int tid  = threadIdx.x;
    const int wid  = tid >> 5;
    const int lane = tid & 31;
    const int wm   = wid & 3;                // 0..3
    const int wn   = wid >> 2;               // 0..1
    // bn fastest (blockIdx.x) so the 4 CTAs sharing an X tile run adjacently -> X hits L2
    const int bn   = blockIdx.x * 128;
    const int bm   = blockIdx.y * 128;

    const uint32_t smem_u = (uint32_t)__cvta_generic_to_shared(smem);

    // loader mapping: row = tid>>1 (0..127), 16-float half-row
    const int lrow = tid >> 1;
    const int lkb  = (tid & 1) * 16;
    const float* xptr = X + (size_t)(bm + lrow) * KDIM + lkb;
    const float* wptr = W + (size_t)(bn + lrow) * KDIM + lkb;

    float acc[2][8][4];
    #pragma unroll
    for (int mt = 0; mt < 2; mt++)
        #pragma unroll
        for (int nt = 0; nt < 8; nt++)
            #pragma unroll
            for (int j = 0; j < 4; j++) acc[mt][nt][j] = 0.f;

    // Prologue: fill 3 stages
    #pragma unroll
    for (int s = 0; s < 3; s++) {
        issue_chunk(smem_u, s, xptr, wptr, s, lrow, lkb);
        CP_COMMIT();
    }

    #pragma unroll 1
    for (int ck = 0; ck < NCHUNK; ck++) {
        CP_WAIT(2);                       // chunk ck's group has landed
        __syncthreads();                  // everyone done with stage (ck+3)&3's old data
        if (ck + 3 < NCHUNK) {
            issue_chunk(smem_u, (ck + 3) & 3, xptr, wptr, ck + 3, lrow, lkb);
            CP_COMMIT();
        }
        compute_chunk(smem + (ck & 3) * STAGEF, acc, wm, wn, lane);
    }

    // Epilogue: direct float2 stores
    #pragma unroll
    for (int mt = 0; mt < 2; mt++) {
        const int r0 = bm + wm * 32 + mt * 16 + (lane >> 2);
        #pragma unroll
        for (int nt = 0; nt < 8; nt++) {
            const int c = bn + wn * 64 + nt * 8 + 2 * (lane & 3);
            *(float2*)(g_I + (size_t)r0 * NDIM + c)       = make_float2(acc[mt][nt][0], acc[mt][nt][1]);
            *(float2*)(g_I + (size_t)(r0 + 8) * NDIM + c) = make_float2(acc[mt][nt][2], acc[mt][nt][3]);
        }
    }
}

// ---------------------------------------------------------------------------
// Kernel 2: per-neuron Izhikevich scan. Incremental pointers, streaming stores.
// ---------------------------------------------------------------------------
struct NeuronP { float TS, V2, V1, V0, KA, Bp, TH, Cc, D; };

__device__ __forceinline__ void snn_step(float Ic, const NeuronP& P,
                                         float& u, float& v,
                                         float*& po, float*& ps)
{
    float t0 = P.V0 - u + Ic;
    t0 = fmaf(P.V1, v, t0);
    t0 = fmaf(P.V2, v * v, t0);
    const float vn = fmaf(P.TS, t0, v);
    const float un = fmaf(P.KA, fmaf(P.Bp, v, -u), u);
    const bool  sp = (vn - P.TH) > 0.f;
    const float s  = sp ? 1.f : 0.f;
    const float vo = sp ? P.Cc : vn;
    const float uo = sp ? (un + P.D) : un;

    *po = s;                      // outputs plane (re-read by reduce) - default policy
    __stcs(ps,             uo);   // states planes: write-only -> streaming
    __stcs(ps + PLANE,     vo);
    __stcs(ps + 2 * PLANE, s);
    po += PLANE;
    ps += 3 * PLANE;
    u = uo; v = vo;
}

__global__ __launch_bounds__(128) void scan_kernel(
    const float* __restrict__ st,
    const float* __restrict__ pa,  const float* __restrict__ pb,
    const float* __restrict__ pc,  const float* __restrict__ pd,
    const float* __restrict__ pv2, const float* __restrict__ pv1,
    const float* __restrict__ pv0, const float* __restrict__ ptau,
    const float* __restrict__ pth, const float* __restrict__ pts,
    float* __restrict__ out)
{
    const int g = blockIdx.x * 128 + threadIdx.x;
    const int n = g & (NDIM - 1);

    NeuronP P;
    P.TS = pts[n];
    P.V2 = pv2[n]; P.V1 = pv1[n]; P.V0 = pv0[n];
    P.KA = P.TS / ptau[n] * pa[n];
    P.Bp = pb[n]; P.TH = pth[n]; P.Cc = pc[n]; P.D = pd[n];

    float u = st[g];
    float v = st[PLANE + g];

    const float* Ip = g_I + (size_t)(g >> 9) * ((size_t)T_STEPS * NDIM) + n;
    float* po = out + g;
    float* ps = out + STATES_OFF + g;

    float bufA[8], bufB[8];
    #pragma unroll
    for (int p = 0; p < 8; p++) bufA[p] = __ldcs(Ip + (size_t)p * NDIM);

    #pragma unroll 1
    for (int t0 = 0; t0 < 992; t0 += 16) {
        #pragma unroll
        for (int p = 0; p < 8; p++) bufB[p] = __ldcs(Ip + (size_t)(8 + p) * NDIM);
        #pragma unroll
        for (int p = 0; p < 8; p++) snn_step(bufA[p], P, u, v, po, ps);
        #pragma unroll
        for (int p = 0; p < 8; p++) bufA[p] = __ldcs(Ip + (size_t)(16 + p) * NDIM);
        #pragma unroll
        for (int p = 0; p < 8; p++) snn_step(bufB[p], P, u, v, po, ps);
        Ip += 16 * NDIM;
    }
    #pragma unroll
    for (int p = 0; p < 8; p++) snn_step(bufA[p], P, u, v, po, ps);
}

// ---------------------------------------------------------------------------
// Kernel 3: r[t*B+b] = sum_n s[t,b,n] * W2[n]   (float4 loads)
// ---------------------------------------------------------------------------
__global__ __launch_bounds__(128) void readout_reduce_kernel(
    const float* __restrict__ out, const float* __restrict__ W2)
{
    const int tb  = blockIdx.x;
    const int tid = threadIdx.x;
    const float4 sv = ((const float4*)(out + (size_t)tb * NDIM))[tid];
    const float4 wv = ((const float4*)W2)[tid];

    float sum = fmaf(sv.x, wv.x, fmaf(sv.y, wv.y, fmaf(sv.z, wv.z, sv.w * wv.w)));
    #pragma unroll
    for (int o = 16; o > 0; o >>= 1)
        sum += __shfl_xor_sync(0xffffffffu, sum, o);

    __shared__ float ws[4];
    if ((tid & 31) == 0) ws[tid >> 5] = sum;
    __syncthreads();
    if (tid == 0) g_r[tb] = (ws[0] + ws[1]) + (ws[2] + ws[3]);
}

// ---------------------------------------------------------------------------
// Kernel 4: li recurrence — warp-parallel linear-recurrence scan, 1 warp per b.
// ---------------------------------------------------------------------------
__global__ void li_kernel(const float* __restrict__ stLI,
                          const float* __restrict__ leak,
                          float* __restrict__ out)
{
    const int b = blockIdx.x;
    const int lane = threadIdx.x;    // 32 threads
    const float lk = leak[0];
    const float l1 = lk, l2 = l1 * l1, l4 = l2 * l2, l8 = l4 * l4, l16 = l8 * l8;
    float lpow = lk;                 // leak^(lane+1)
    {
        float sq[5] = {l1, l2, l4, l8, l16};
        #pragma unroll
        for (int i = 0; i < 5; i++)
            if ((lane >> i) & 1) lpow *= sq[i];
    }

    float carry = stLI[b];
    float x = g_r[lane * BATCH + b];

    #pragma unroll 1
    for (int t0 = 0; t0 < T_STEPS; t0 += 32) {
        const int tn = t0 + 32 + lane;
        const float xn = (tn < T_STEPS) ? g_r[tn * BATCH + b] : 0.f;

        float y = x, up;
        up = __shfl_up_sync(0xffffffffu, y, 1);  if (lane >= 1)  y = fmaf(l1,  up, y);
        up = __shfl_up_sync(0xffffffffu, y, 2);  if (lane >= 2)  y = fmaf(l2,  up, y);
        up = __shfl_up_sync(0xffffffffu, y, 4);  if (lane >= 4)  y = fmaf(l4,  up, y);
        up = __shfl_up_sync(0xffffffffu, y, 8);  if (lane >= 8)  y = fmaf(l8,  up, y);
        up = __shfl_up_sync(0xffffffffu, y, 16); if (lane >= 16) y = fmaf(l16, up, y);

        const float li = fmaf(lpow, carry, y);
        if (t0 + lane < T_STEPS)
            out[DEC_OFF + (size_t)(t0 + lane) * BATCH + b] = li;
        carry = __shfl_sync(0xffffffffu, li, 31);
        x = xn;
    }
}

// ---------------------------------------------------------------------------
extern "C" void kernel_launch(void* const* d_in, const int* in_sizes, int n_in,
                              void* d_out, int out_size)
{
    const float* x    = (const float*)d_in[0];
    const float* st   = (const float*)d_in[1];
    const float* stLI = (const float*)d_in[2];
    const float* W1   = (const float*)d_in[3];
    const float* W2   = (const float*)d_in[4];
    const float* a_   = (const float*)d_in[5];
    const float* b_   = (const float*)d_in[6];
    const float* c_   = (const float*)d_in[7];
    const float* d_   = (const float*)d_in[8];
    const float* v2_  = (const float*)d_in[9];
    const float* v1_  = (const float*)d_in[10];
    const float* v0_  = (const float*)d_in[11];
    const float* tau_ = (const float*)d_in[12];
    const float* th_  = (const float*)d_in[13];
    const float* lk_  = (const float*)d_in[14];
    const float* ts_  = (const float*)d_in[15];
    float* out = (float*)d_out;

    const int smem_bytes = 4 * STAGEF * (int)sizeof(float);   // 147456
    cudaFuncSetAttribute(gemm_tf32_kernel,
                         cudaFuncAttributeMaxDynamicSharedMemorySize, smem_bytes);

    dim3 ggrid(NDIM / 128, MROWS / 128);   // (4, 500): bn fastest for X-tile L2 reuse
    gemm_tf32_kernel<<<ggrid, 256, smem_bytes>>>(x, W1);
    scan_kernel<<<(BATCH * NDIM) / 128, 128>>>(st, a_, b_, c_, d_, v2_, v1_,
                                               v0_, tau_, th_, ts_, out);
    readout_reduce_kernel<<<T_STEPS * BATCH, 128>>>(out, W2);
    li_kernel<<<BATCH, 32>>>(stLI, lk_, out);
}